// round 1
// baseline (speedup 1.0000x reference)
#include <cuda_runtime.h>
#include <math.h>

#define NROWS 32768
#define DIMS  256
#define CODES 4096
#define TM 64
#define TN 64
#define NBLOCKS (NROWS/TM)

// Dynamic smem layout (floats unless noted):
//   As   [DIMS][TM]      = 16384 floats
//   Bs   [2][32][TN]     =  4096 floats
//   sXsq [TM]            =    64 floats
//   sBV  [TM][16]        =  1024 floats
//   sBI  [TM][16]        =  1024 ints
//   sRed [8]             =     8 doubles
#define SMEM_BYTES ((16384 + 4096 + 64 + 1024) * 4 + 1024 * 4 + 8 * 8)

__device__ float  g_xsq[NROWS];
__device__ float  g_esq[CODES];
__device__ int    g_counts[CODES];
__device__ double g_lossPartial[NBLOCKS];

__global__ void k_setup(const float* __restrict__ x, const float* __restrict__ cb) {
    int i = blockIdx.x * blockDim.x + threadIdx.x;
    if (i < NROWS) {
        const float4* p = reinterpret_cast<const float4*>(x) + i * (DIMS / 4);
        double s = 0.0;
        #pragma unroll 8
        for (int j = 0; j < DIMS / 4; j++) {
            float4 v = p[j];
            s += (double)v.x * v.x + (double)v.y * v.y
               + (double)v.z * v.z + (double)v.w * v.w;
        }
        g_xsq[i] = (float)s;
    }
    if (i < CODES) {
        g_counts[i] = 0;
        const float4* p = reinterpret_cast<const float4*>(cb) + i * (DIMS / 4);
        double s = 0.0;
        #pragma unroll 8
        for (int j = 0; j < DIMS / 4; j++) {
            float4 v = p[j];
            s += (double)v.x * v.x + (double)v.y * v.y
               + (double)v.z * v.z + (double)v.w * v.w;
        }
        g_esq[i] = (float)s;
    }
}

__global__ __launch_bounds__(256, 2)
void k_main(const float* __restrict__ x, const float* __restrict__ cb,
            float* __restrict__ out) {
    extern __shared__ char smraw[];
    float*  As   = reinterpret_cast<float*>(smraw);
    float*  Bs   = As + DIMS * TM;
    float*  sXsq = Bs + 2 * 32 * TN;
    float*  sBV  = sXsq + TM;
    int*    sBI  = reinterpret_cast<int*>(sBV + TM * 16);
    double* sRed = reinterpret_cast<double*>(sBI + TM * 16);

    const int t  = threadIdx.x;          // 256 threads
    const int tx = t & 15;               // code-group
    const int ty = t >> 4;               // row-group
    const int rowBase = blockIdx.x * TM;

    // ---- Load x tile transposed into smem: As[d][r] ----
    for (int i = t; i < TM * (DIMS / 4); i += 256) {
        int r  = i >> 6;                 // 64 float4 per row
        int d4 = i & 63;
        float4 v = *reinterpret_cast<const float4*>(
            x + (size_t)(rowBase + r) * DIMS + d4 * 4);
        As[(d4 * 4 + 0) * TM + r] = v.x;
        As[(d4 * 4 + 1) * TM + r] = v.y;
        As[(d4 * 4 + 2) * TM + r] = v.z;
        As[(d4 * 4 + 3) * TM + r] = v.w;
    }
    if (t < TM) sXsq[t] = g_xsq[rowBase + t];
    __syncthreads();

    float rXsq[4];
    #pragma unroll
    for (int i = 0; i < 4; i++) rXsq[i] = sXsq[ty * 4 + i];

    float bestV[4];
    int   bestI[4];
    #pragma unroll
    for (int i = 0; i < 4; i++) { bestV[i] = 3.4e38f; bestI[i] = 0; }

    // B-tile load assignment: 512 float4 per chunk, 2 per thread
    const int c0  = (t * 2) >> 3;
    const int d40 = (t * 2) & 7;
    const int c1  = (t * 2 + 1) >> 3;
    const int d41 = (t * 2 + 1) & 7;

    for (int ct = 0; ct < CODES / TN; ct++) {
        float eq[4];
        #pragma unroll
        for (int j = 0; j < 4; j++) eq[j] = g_esq[ct * TN + tx * 4 + j];

        float acc[4][4];
        #pragma unroll
        for (int i = 0; i < 4; i++)
            #pragma unroll
            for (int j = 0; j < 4; j++) acc[i][j] = 0.0f;

        // preload d-chunk 0 into buffer 0
        {
            float4 v0 = *reinterpret_cast<const float4*>(
                cb + (size_t)(ct * TN + c0) * DIMS + d40 * 4);
            float4 v1 = *reinterpret_cast<const float4*>(
                cb + (size_t)(ct * TN + c1) * DIMS + d41 * 4);
            float* p0 = Bs + (d40 * 4) * TN + c0;
            p0[0] = v0.x; p0[TN] = v0.y; p0[2 * TN] = v0.z; p0[3 * TN] = v0.w;
            float* p1 = Bs + (d41 * 4) * TN + c1;
            p1[0] = v1.x; p1[TN] = v1.y; p1[2 * TN] = v1.z; p1[3 * TN] = v1.w;
        }
        __syncthreads();

        #pragma unroll
        for (int dc = 0; dc < 8; dc++) {
            const int buf = dc & 1;
            float4 n0, n1;
            if (dc < 7) {
                n0 = *reinterpret_cast<const float4*>(
                    cb + (size_t)(ct * TN + c0) * DIMS + (dc + 1) * 32 + d40 * 4);
                n1 = *reinterpret_cast<const float4*>(
                    cb + (size_t)(ct * TN + c1) * DIMS + (dc + 1) * 32 + d41 * 4);
            }
            const float* Bb = Bs + buf * (32 * TN);
            const float* Ab = As + dc * 32 * TM;
            #pragma unroll
            for (int dd = 0; dd < 32; dd++) {
                float4 a = *reinterpret_cast<const float4*>(Ab + dd * TM + ty * 4);
                float4 b = *reinterpret_cast<const float4*>(Bb + dd * TN + tx * 4);
                const float av[4] = {a.x, a.y, a.z, a.w};
                const float bv[4] = {b.x, b.y, b.z, b.w};
                #pragma unroll
                for (int i = 0; i < 4; i++)
                    #pragma unroll
                    for (int j = 0; j < 4; j++)
                        acc[i][j] = fmaf(av[i], bv[j], acc[i][j]);
            }
            if (dc < 7) {
                float* nb = Bs + (buf ^ 1) * (32 * TN);
                float* p0 = nb + (d40 * 4) * TN + c0;
                p0[0] = n0.x; p0[TN] = n0.y; p0[2 * TN] = n0.z; p0[3 * TN] = n0.w;
                float* p1 = nb + (d41 * 4) * TN + c1;
                p1[0] = n1.x; p1[TN] = n1.y; p1[2 * TN] = n1.z; p1[3 * TN] = n1.w;
            }
            __syncthreads();
        }

        // distances (reference expression structure) + running argmin
        #pragma unroll
        for (int i = 0; i < 4; i++) {
            #pragma unroll
            for (int j = 0; j < 4; j++) {
                float dist = __fadd_rn(__fadd_rn(rXsq[i], eq[j]), -2.0f * acc[i][j]);
                if (dist < bestV[i]) { bestV[i] = dist; bestI[i] = ct * TN + tx * 4 + j; }
            }
        }
    }

    // ---- cross-thread argmin reduce (lowest-index tie break, as jnp.argmin) ----
    #pragma unroll
    for (int i = 0; i < 4; i++) {
        sBV[(ty * 4 + i) * 16 + tx] = bestV[i];
        sBI[(ty * 4 + i) * 16 + tx] = bestI[i];
    }
    __syncthreads();
    if (t < TM) {
        float bv = sBV[t * 16];
        int   bi = sBI[t * 16];
        #pragma unroll
        for (int j = 1; j < 16; j++) {
            float v = sBV[t * 16 + j];
            int   c = sBI[t * 16 + j];
            if (v < bv || (v == bv && c < bi)) { bv = v; bi = c; }
        }
        sBI[t * 16] = bi;
        atomicAdd(&g_counts[bi], 1);
    }
    __syncthreads();

    // ---- quantized gather + write + per-block fp64 loss partial ----
    const int row  = t >> 2;             // 4 threads per row
    const int part = t & 3;
    const int best = sBI[row * 16];
    const float4* qsrc =
        reinterpret_cast<const float4*>(cb + (size_t)best * DIMS) + part * 16;
    float4* qdst =
        reinterpret_cast<float4*>(out + (size_t)(rowBase + row) * DIMS) + part * 16;
    double lsum = 0.0;
    #pragma unroll
    for (int u = 0; u < 16; u++) {
        float4 q = qsrc[u];
        int d0 = part * 64 + u * 4;
        float dx0 = q.x - As[(d0 + 0) * TM + row];
        float dx1 = q.y - As[(d0 + 1) * TM + row];
        float dx2 = q.z - As[(d0 + 2) * TM + row];
        float dx3 = q.w - As[(d0 + 3) * TM + row];
        lsum += (double)dx0 * dx0 + (double)dx1 * dx1
              + (double)dx2 * dx2 + (double)dx3 * dx3;
        qdst[u] = q;
    }
    #pragma unroll
    for (int o = 16; o > 0; o >>= 1)
        lsum += __shfl_down_sync(0xffffffffu, lsum, o);
    if ((t & 31) == 0) sRed[t >> 5] = lsum;
    __syncthreads();
    if (t == 0) {
        double s = 0.0;
        #pragma unroll
        for (int w = 0; w < 8; w++) s += sRed[w];
        g_lossPartial[blockIdx.x] = s;   // deterministic: fixed-order reduction
    }
}

__global__ void k_final(float* __restrict__ out, int out_size) {
    __shared__ double red[256];
    int t = threadIdx.x;

    double ls = 0.0;
    for (int i = t; i < NBLOCKS; i += 256) ls += g_lossPartial[i];
    red[t] = ls;
    __syncthreads();
    for (int o = 128; o > 0; o >>= 1) {
        if (t < o) red[t] += red[t + o];
        __syncthreads();
    }
    double lossTot = red[0];
    __syncthreads();

    double es = 0.0;
    for (int i = t; i < CODES; i += 256) {
        double p = (double)g_counts[i] * (1.0 / (double)NROWS);
        es += p * log(p + 1e-10);
    }
    red[t] = es;
    __syncthreads();
    for (int o = 128; o > 0; o >>= 1) {
        if (t < o) red[t] += red[t + o];
        __syncthreads();
    }

    if (t == 0 && out_size >= NROWS * DIMS + 2) {
        double mse = lossTot / (double)((size_t)NROWS * DIMS);
        out[NROWS * DIMS]     = (float)(mse * 1.25);     // codebook + 0.25*commitment
        out[NROWS * DIMS + 1] = (float)exp(-red[0]);     // perplexity
    }
}

extern "C" void kernel_launch(void* const* d_in, const int* in_sizes, int n_in,
                              void* d_out, int out_size) {
    const float* x  = (const float*)d_in[0];
    const float* cb = (const float*)d_in[1];
    // defensive: detect order by size (x has 8388608 elems, codebook 1048576)
    if (n_in >= 2 && in_sizes[0] == CODES * DIMS && in_sizes[1] == NROWS * DIMS) {
        const float* tmp = x; x = cb; cb = tmp;
    }
    float* out = (float*)d_out;

    cudaFuncSetAttribute(k_main, cudaFuncAttributeMaxDynamicSharedMemorySize,
                         SMEM_BYTES);

    k_setup<<<(NROWS + 255) / 256, 256>>>(x, cb);
    k_main<<<NBLOCKS, 256, SMEM_BYTES>>>(x, cb, out);
    k_final<<<1, 256>>>(out, out_size);
}

// round 2
// speedup vs baseline: 1.0020x; 1.0020x over previous
#include <cuda_runtime.h>
#include <math.h>

#define NROWS 32768
#define DIMS  256
#define CODES 4096
#define TM 64
#define TN 64
#define NBLOCKS (NROWS/TM)

// Dynamic smem layout (floats unless noted):
//   As   [DIMS][TM]      = 16384 floats
//   Bs   [2][32][TN]     =  4096 floats
//   sXsq [TM]            =    64 floats
//   sBV  [TM][16]        =  1024 floats
//   sBI  [TM][16]        =  1024 ints
//   sRed [8]             =     8 doubles
#define SMEM_BYTES ((16384 + 4096 + 64 + 1024) * 4 + 1024 * 4 + 8 * 8)

__device__ float  g_xsq[NROWS];
__device__ float  g_esq[CODES];
__device__ int    g_counts[CODES];
__device__ double g_lossPartial[NBLOCKS];

__global__ void k_setup(const float* __restrict__ x, const float* __restrict__ cb) {
    int i = blockIdx.x * blockDim.x + threadIdx.x;
    if (i < NROWS) {
        const float4* p = reinterpret_cast<const float4*>(x) + i * (DIMS / 4);
        double s = 0.0;
        #pragma unroll 8
        for (int j = 0; j < DIMS / 4; j++) {
            float4 v = p[j];
            s += (double)v.x * v.x + (double)v.y * v.y
               + (double)v.z * v.z + (double)v.w * v.w;
        }
        g_xsq[i] = (float)s;
    }
    if (i < CODES) {
        g_counts[i] = 0;
        const float4* p = reinterpret_cast<const float4*>(cb) + i * (DIMS / 4);
        double s = 0.0;
        #pragma unroll 8
        for (int j = 0; j < DIMS / 4; j++) {
            float4 v = p[j];
            s += (double)v.x * v.x + (double)v.y * v.y
               + (double)v.z * v.z + (double)v.w * v.w;
        }
        g_esq[i] = (float)s;
    }
}

__global__ __launch_bounds__(256, 2)
void k_main(const float* __restrict__ x, const float* __restrict__ cb,
            float* __restrict__ out) {
    extern __shared__ char smraw[];
    float*  As   = reinterpret_cast<float*>(smraw);
    float*  Bs   = As + DIMS * TM;
    float*  sXsq = Bs + 2 * 32 * TN;
    float*  sBV  = sXsq + TM;
    int*    sBI  = reinterpret_cast<int*>(sBV + TM * 16);
    double* sRed = reinterpret_cast<double*>(sBI + TM * 16);

    const int t  = threadIdx.x;          // 256 threads
    const int tx = t & 15;               // code-group
    const int ty = t >> 4;               // row-group
    const int rowBase = blockIdx.x * TM;

    // ---- Load x tile transposed into smem: As[d][r] ----
    for (int i = t; i < TM * (DIMS / 4); i += 256) {
        int r  = i >> 6;                 // 64 float4 per row
        int d4 = i & 63;
        float4 v = *reinterpret_cast<const float4*>(
            x + (size_t)(rowBase + r) * DIMS + d4 * 4);
        As[(d4 * 4 + 0) * TM + r] = v.x;
        As[(d4 * 4 + 1) * TM + r] = v.y;
        As[(d4 * 4 + 2) * TM + r] = v.z;
        As[(d4 * 4 + 3) * TM + r] = v.w;
    }
    if (t < TM) sXsq[t] = g_xsq[rowBase + t];
    __syncthreads();

    float rXsq[4];
    #pragma unroll
    for (int i = 0; i < 4; i++) rXsq[i] = sXsq[ty * 4 + i];

    float bestV[4];
    int   bestI[4];
    #pragma unroll
    for (int i = 0; i < 4; i++) { bestV[i] = 3.4e38f; bestI[i] = 0; }

    // B-tile load assignment: 512 float4 per chunk, 2 per thread
    const int c0  = (t * 2) >> 3;
    const int d40 = (t * 2) & 7;
    const int c1  = (t * 2 + 1) >> 3;
    const int d41 = (t * 2 + 1) & 7;

    for (int ct = 0; ct < CODES / TN; ct++) {
        float eq[4];
        #pragma unroll
        for (int j = 0; j < 4; j++) eq[j] = g_esq[ct * TN + tx * 4 + j];

        float acc[4][4];
        #pragma unroll
        for (int i = 0; i < 4; i++)
            #pragma unroll
            for (int j = 0; j < 4; j++) acc[i][j] = 0.0f;

        // preload d-chunk 0 into buffer 0
        {
            float4 v0 = *reinterpret_cast<const float4*>(
                cb + (size_t)(ct * TN + c0) * DIMS + d40 * 4);
            float4 v1 = *reinterpret_cast<const float4*>(
                cb + (size_t)(ct * TN + c1) * DIMS + d41 * 4);
            float* p0 = Bs + (d40 * 4) * TN + c0;
            p0[0] = v0.x; p0[TN] = v0.y; p0[2 * TN] = v0.z; p0[3 * TN] = v0.w;
            float* p1 = Bs + (d41 * 4) * TN + c1;
            p1[0] = v1.x; p1[TN] = v1.y; p1[2 * TN] = v1.z; p1[3 * TN] = v1.w;
        }
        __syncthreads();

        #pragma unroll
        for (int dc = 0; dc < 8; dc++) {
            const int buf = dc & 1;
            float4 n0, n1;
            if (dc < 7) {
                n0 = *reinterpret_cast<const float4*>(
                    cb + (size_t)(ct * TN + c0) * DIMS + (dc + 1) * 32 + d40 * 4);
                n1 = *reinterpret_cast<const float4*>(
                    cb + (size_t)(ct * TN + c1) * DIMS + (dc + 1) * 32 + d41 * 4);
            }
            const float* Bb = Bs + buf * (32 * TN);
            const float* Ab = As + dc * 32 * TM;
            #pragma unroll
            for (int dd = 0; dd < 32; dd++) {
                float4 a = *reinterpret_cast<const float4*>(Ab + dd * TM + ty * 4);
                float4 b = *reinterpret_cast<const float4*>(Bb + dd * TN + tx * 4);
                const float av[4] = {a.x, a.y, a.z, a.w};
                const float bv[4] = {b.x, b.y, b.z, b.w};
                #pragma unroll
                for (int i = 0; i < 4; i++)
                    #pragma unroll
                    for (int j = 0; j < 4; j++)
                        acc[i][j] = fmaf(av[i], bv[j], acc[i][j]);
            }
            if (dc < 7) {
                float* nb = Bs + (buf ^ 1) * (32 * TN);
                float* p0 = nb + (d40 * 4) * TN + c0;
                p0[0] = n0.x; p0[TN] = n0.y; p0[2 * TN] = n0.z; p0[3 * TN] = n0.w;
                float* p1 = nb + (d41 * 4) * TN + c1;
                p1[0] = n1.x; p1[TN] = n1.y; p1[2 * TN] = n1.z; p1[3 * TN] = n1.w;
            }
            __syncthreads();
        }

        // distances (reference expression structure) + running argmin
        #pragma unroll
        for (int i = 0; i < 4; i++) {
            #pragma unroll
            for (int j = 0; j < 4; j++) {
                float dist = __fadd_rn(__fadd_rn(rXsq[i], eq[j]), -2.0f * acc[i][j]);
                if (dist < bestV[i]) { bestV[i] = dist; bestI[i] = ct * TN + tx * 4 + j; }
            }
        }
    }

    // ---- cross-thread argmin reduce (lowest-index tie break, as jnp.argmin) ----
    #pragma unroll
    for (int i = 0; i < 4; i++) {
        sBV[(ty * 4 + i) * 16 + tx] = bestV[i];
        sBI[(ty * 4 + i) * 16 + tx] = bestI[i];
    }
    __syncthreads();
    if (t < TM) {
        float bv = sBV[t * 16];
        int   bi = sBI[t * 16];
        #pragma unroll
        for (int j = 1; j < 16; j++) {
            float v = sBV[t * 16 + j];
            int   c = sBI[t * 16 + j];
            if (v < bv || (v == bv && c < bi)) { bv = v; bi = c; }
        }
        sBI[t * 16] = bi;
        atomicAdd(&g_counts[bi], 1);
    }
    __syncthreads();

    // ---- quantized gather + write + per-block fp64 loss partial ----
    const int row  = t >> 2;             // 4 threads per row
    const int part = t & 3;
    const int best = sBI[row * 16];
    const float4* qsrc =
        reinterpret_cast<const float4*>(cb + (size_t)best * DIMS) + part * 16;
    float4* qdst =
        reinterpret_cast<float4*>(out + (size_t)(rowBase + row) * DIMS) + part * 16;
    double lsum = 0.0;
    #pragma unroll
    for (int u = 0; u < 16; u++) {
        float4 q = qsrc[u];
        int d0 = part * 64 + u * 4;
        float dx0 = q.x - As[(d0 + 0) * TM + row];
        float dx1 = q.y - As[(d0 + 1) * TM + row];
        float dx2 = q.z - As[(d0 + 2) * TM + row];
        float dx3 = q.w - As[(d0 + 3) * TM + row];
        lsum += (double)dx0 * dx0 + (double)dx1 * dx1
              + (double)dx2 * dx2 + (double)dx3 * dx3;
        qdst[u] = q;
    }
    #pragma unroll
    for (int o = 16; o > 0; o >>= 1)
        lsum += __shfl_down_sync(0xffffffffu, lsum, o);
    if ((t & 31) == 0) sRed[t >> 5] = lsum;
    __syncthreads();
    if (t == 0) {
        double s = 0.0;
        #pragma unroll
        for (int w = 0; w < 8; w++) s += sRed[w];
        g_lossPartial[blockIdx.x] = s;   // deterministic: fixed-order reduction
    }
}

__global__ void k_final(float* __restrict__ out, int out_size) {
    __shared__ double red[256];
    int t = threadIdx.x;

    double ls = 0.0;
    for (int i = t; i < NBLOCKS; i += 256) ls += g_lossPartial[i];
    red[t] = ls;
    __syncthreads();
    for (int o = 128; o > 0; o >>= 1) {
        if (t < o) red[t] += red[t + o];
        __syncthreads();
    }
    double lossTot = red[0];
    __syncthreads();

    double es = 0.0;
    for (int i = t; i < CODES; i += 256) {
        double p = (double)g_counts[i] * (1.0 / (double)NROWS);
        es += p * log(p + 1e-10);
    }
    red[t] = es;
    __syncthreads();
    for (int o = 128; o > 0; o >>= 1) {
        if (t < o) red[t] += red[t + o];
        __syncthreads();
    }

    if (t == 0 && out_size >= NROWS * DIMS + 2) {
        double mse = lossTot / (double)((size_t)NROWS * DIMS);
        out[NROWS * DIMS]     = (float)(mse * 1.25);     // codebook + 0.25*commitment
        out[NROWS * DIMS + 1] = (float)exp(-red[0]);     // perplexity
    }
}

extern "C" void kernel_launch(void* const* d_in, const int* in_sizes, int n_in,
                              void* d_out, int out_size) {
    const float* x  = (const float*)d_in[0];
    const float* cb = (const float*)d_in[1];
    // defensive: detect order by size (x has 8388608 elems, codebook 1048576)
    if (n_in >= 2 && in_sizes[0] == CODES * DIMS && in_sizes[1] == NROWS * DIMS) {
        const float* tmp = x; x = cb; cb = tmp;
    }
    float* out = (float*)d_out;

    cudaFuncSetAttribute(k_main, cudaFuncAttributeMaxDynamicSharedMemorySize,
                         SMEM_BYTES);

    k_setup<<<(NROWS + 255) / 256, 256>>>(x, cb);
    k_main<<<NBLOCKS, 256, SMEM_BYTES>>>(x, cb, out);
    k_final<<<1, 256>>>(out, out_size);
}

// round 4
// speedup vs baseline: 2.8097x; 2.8040x over previous
#include <cuda_runtime.h>
#include <cuda_fp16.h>
#include <math.h>
#include <cstdint>

#define NROWS 32768
#define DIMS  256
#define CODES 4096
#define BM 128
#define BN 128
#define NCH   (CODES/BN)    // 32
#define NCTAS (NROWS/BM)    // 256
#define GITER (NCH*8)       // 256 k-chunk iterations (8 per n-chunk)

// smem byte offsets
#define OFF_AH   0
#define OFF_AL   65536
#define OFF_B    131072
#define B_BUF    10240      // 128 rows * 80B (64B data + 16B pad)
#define OFF_ESQ  172032
#define OFF_XSQ  188416
#define OFF_RV   188928
#define OFF_RI   197120
#define OFF_LOSS 205312
#define SMEM_SZ  205376

// packed-f16 scratch (2 halves per uint32)
__device__ uint32_t g_xh[NROWS*DIMS/2];
__device__ uint32_t g_xl[NROWS*DIMS/2];
__device__ uint32_t g_eh[CODES*DIMS/2];
__device__ uint32_t g_el[CODES*DIMS/2];
__device__ float  g_xsq[NROWS];
__device__ float  g_esq[CODES];
__device__ int    g_counts[CODES];
__device__ double g_lossPartial[NCTAS];

__device__ __forceinline__ uint32_t smem_u32(const void* p) {
    uint32_t a;
    asm("{ .reg .u64 t; cvta.to.shared.u64 t, %1; cvt.u32.u64 %0, t; }" : "=r"(a) : "l"(p));
    return a;
}
#define CP_ASYNC16(dst, src) \
    asm volatile("cp.async.cg.shared.global [%0], [%1], 16;" :: "r"((uint32_t)(dst)), "l"(src) : "memory")
#define CP_COMMIT() asm volatile("cp.async.commit_group;" ::: "memory")
#define CP_WAIT0()  asm volatile("cp.async.wait_group 0;" ::: "memory")
#define LDM_X4(r, a) \
    asm volatile("ldmatrix.sync.aligned.m8n8.x4.shared.b16 {%0,%1,%2,%3}, [%4];" \
        : "=r"((r)[0]), "=r"((r)[1]), "=r"((r)[2]), "=r"((r)[3]) : "r"(a))
#define MMA16816(c, a, b) \
    asm volatile("mma.sync.aligned.m16n8k16.row.col.f32.f16.f16.f32 " \
        "{%0,%1,%2,%3}, {%4,%5,%6,%7}, {%8,%9}, {%0,%1,%2,%3};" \
        : "+f"((c)[0]), "+f"((c)[1]), "+f"((c)[2]), "+f"((c)[3]) \
        : "r"((a)[0]), "r"((a)[1]), "r"((a)[2]), "r"((a)[3]), "r"((b)[0]), "r"((b)[1]))

__global__ void k_setup(const float* __restrict__ x, const float* __restrict__ cb) {
    int i = blockIdx.x * blockDim.x + threadIdx.x;
    if (i < NROWS) {
        const float4* p = reinterpret_cast<const float4*>(x) + i * (DIMS/4);
        double s = 0.0;
        #pragma unroll 8
        for (int j = 0; j < DIMS/4; j++) {
            float4 v = p[j];
            s += (double)v.x*v.x + (double)v.y*v.y + (double)v.z*v.z + (double)v.w*v.w;
        }
        g_xsq[i] = (float)s;
    }
    if (i < CODES) {
        g_counts[i] = 0;
        const float4* p = reinterpret_cast<const float4*>(cb) + i * (DIMS/4);
        double s = 0.0;
        #pragma unroll 8
        for (int j = 0; j < DIMS/4; j++) {
            float4 v = p[j];
            s += (double)v.x*v.x + (double)v.y*v.y + (double)v.z*v.z + (double)v.w*v.w;
        }
        g_esq[i] = (float)s;
    }
}

__device__ __forceinline__ uint32_t pack_hl(float a, float b, float& ra, float& rb) {
    __half ha = __float2half_rn(a), hb = __float2half_rn(b);
    ra = a - __half2float(ha); rb = b - __half2float(hb);
    return (uint32_t)__half_as_ushort(ha) | ((uint32_t)__half_as_ushort(hb) << 16);
}
__device__ __forceinline__ uint32_t pack_lo(float a, float b) {
    return (uint32_t)__half_as_ushort(__float2half_rn(a)) |
           ((uint32_t)__half_as_ushort(__float2half_rn(b)) << 16);
}

__global__ void k_prep(const float* __restrict__ x, const float* __restrict__ cb) {
    const int NX4 = NROWS*DIMS/4, NC4 = CODES*DIMS/4;
    int i = blockIdx.x * blockDim.x + threadIdx.x;
    if (i < NX4) {
        float4 v = reinterpret_cast<const float4*>(x)[i];
        float rx, ry, rz, rw;
        uint32_t h0 = pack_hl(v.x, v.y, rx, ry);
        uint32_t h1 = pack_hl(v.z, v.w, rz, rw);
        g_xh[2*i] = h0; g_xh[2*i+1] = h1;
        g_xl[2*i] = pack_lo(rx, ry); g_xl[2*i+1] = pack_lo(rz, rw);
    } else if (i < NX4 + NC4) {
        int j = i - NX4;
        float4 v = reinterpret_cast<const float4*>(cb)[j];
        v.x *= 4096.0f; v.y *= 4096.0f; v.z *= 4096.0f; v.w *= 4096.0f;
        float rx, ry, rz, rw;
        uint32_t h0 = pack_hl(v.x, v.y, rx, ry);
        uint32_t h1 = pack_hl(v.z, v.w, rz, rw);
        g_eh[2*j] = h0; g_eh[2*j+1] = h1;
        g_el[2*j] = pack_lo(rx, ry); g_el[2*j+1] = pack_lo(rz, rw);
    }
}

__device__ __forceinline__ void prefetchB(uint32_t smb, int stage, int gc, int t) {
    const int nc = gc >> 3, kch = gc & 7;
    #pragma unroll
    for (int j = 0; j < 4; j++) {
        int i = t + 256*j;
        int arr = i >> 9, rem = i & 511, row = rem >> 2, c = rem & 3;
        uint32_t so = smb + OFF_B + (uint32_t)(stage*2 + arr)*B_BUF + row*80 + c*16;
        const uint8_t* src = (const uint8_t*)(arr ? g_el : g_eh)
                           + (size_t)(nc*BN + row)*512 + (size_t)kch*64 + c*16;
        CP_ASYNC16(so, src);
    }
}

__global__ void __launch_bounds__(256, 1) k_tc(const float* __restrict__ x,
        const float* __restrict__ cb, float* __restrict__ out)
{
    extern __shared__ char sm[];
    const uint32_t smb = smem_u32(sm);
    const int t = threadIdx.x, w = t >> 5, lane = t & 31;
    const int wm = w & 1, wn = w >> 1;
    const int group = lane >> 2, tid4 = lane & 3;
    const int rowBase = blockIdx.x * BM;

    // A tiles (xh, xl) resident: 128 rows x 256 halves, XOR-swizzled (chunk ^ row&7)
    #pragma unroll 4
    for (int j = 0; j < 32; j++) {
        int i = t + 256*j;
        int arr = i >> 12, rem = i & 4095, row = rem >> 5, c = rem & 31;
        uint32_t so = smb + (arr ? OFF_AL : OFF_AH) + row*512 + ((c ^ (row & 7)) * 16);
        const uint8_t* src = (const uint8_t*)(arr ? g_xl : g_xh)
                           + (size_t)(rowBase + row)*512 + c*16;
        CP_ASYNC16(so, src);
    }
    float* sEsq = (float*)(sm + OFF_ESQ);
    float* sXsq = (float*)(sm + OFF_XSQ);
    for (int i = t; i < CODES; i += 256) sEsq[i] = g_esq[i];
    for (int i = t; i < BM;    i += 256) sXsq[i] = g_xsq[rowBase + i];
    prefetchB(smb, 0, 0, t);
    CP_COMMIT();

    float C[4][4][4];
    float bestV[8];
    int   bestI[8];
    #pragma unroll
    for (int s = 0; s < 8; s++) { bestV[s] = 3.4e38f; bestI[s] = 0; }

    const uint32_t aRow = (uint32_t)(wm*64 + (lane & 15));
    const uint32_t aSwz = (uint32_t)(lane & 7);
    const uint32_t aKhi = (uint32_t)(lane >> 4);

    for (int gi = 0; gi < GITER; ++gi) {
        const int stage = gi & 1;
        CP_WAIT0();
        __syncthreads();
        if (gi + 1 < GITER) { prefetchB(smb, stage ^ 1, gi + 1, t); CP_COMMIT(); }
        if ((gi & 7) == 0) {
            #pragma unroll
            for (int mt = 0; mt < 4; mt++)
                #pragma unroll
                for (int nt = 0; nt < 4; nt++)
                    #pragma unroll
                    for (int q = 0; q < 4; q++) C[mt][nt][q] = 0.0f;
        }
        #pragma unroll
        for (int ks = 0; ks < 2; ++ks) {
            const int kc16 = (gi & 7)*2 + ks;
            uint32_t ah[4][4], al[4][4];
            #pragma unroll
            for (int mt = 0; mt < 4; mt++) {
                uint32_t chunk = ((uint32_t)(kc16*2) + aKhi) ^ aSwz;
                uint32_t ad = smb + OFF_AH + (aRow + mt*16)*512 + chunk*16;
                LDM_X4(ah[mt], ad);
                LDM_X4(al[mt], ad + (OFF_AL - OFF_AH));
            }
            uint32_t bh[4][2], bl[4][2];
            #pragma unroll
            for (int nt = 0; nt < 4; nt++) {
                uint32_t bd = OFF_B + (uint32_t)(stage*2)*B_BUF
                            + (uint32_t)(wn*32 + nt*8 + group)*80 + ks*32 + tid4*4;
                bh[nt][0] = *(const uint32_t*)(sm + bd);
                bh[nt][1] = *(const uint32_t*)(sm + bd + 16);
                bl[nt][0] = *(const uint32_t*)(sm + bd + B_BUF);
                bl[nt][1] = *(const uint32_t*)(sm + bd + B_BUF + 16);
            }
            #pragma unroll
            for (int mt = 0; mt < 4; mt++)
                #pragma unroll
                for (int nt = 0; nt < 4; nt++) {
                    MMA16816(C[mt][nt], ah[mt], bh[nt]);
                    MMA16816(C[mt][nt], al[mt], bh[nt]);
                    MMA16816(C[mt][nt], ah[mt], bl[nt]);
                }
        }
        if ((gi & 7) == 7) {
            const int nc = gi >> 3;
            #pragma unroll
            for (int mt = 0; mt < 4; mt++)
                #pragma unroll
                for (int h = 0; h < 2; h++) {
                    const int slot = mt*2 + h;
                    const float xs = sXsq[wm*64 + mt*16 + group + 8*h];
                    #pragma unroll
                    for (int nt = 0; nt < 4; nt++)
                        #pragma unroll
                        for (int q = 0; q < 2; q++) {
                            const int col = nc*BN + wn*32 + nt*8 + tid4*2 + q;
                            const float se = __fadd_rn(xs, sEsq[col]);
                            const float d = fmaf(-0.00048828125f, C[mt][nt][h*2 + q], se);
                            if (d < bestV[slot]) { bestV[slot] = d; bestI[slot] = col; }
                        }
                }
        }
    }
    __syncthreads();

    float* sRV = (float*)(sm + OFF_RV);
    int*   sRI = (int*)(sm + OFF_RI);
    #pragma unroll
    for (int mt = 0; mt < 4; mt++)
        #pragma unroll
        for (int h = 0; h < 2; h++) {
            const int row  = wm*64 + mt*16 + group + 8*h;
            const int slot = wn*4 + tid4;
            sRV[row*16 + slot] = bestV[mt*2 + h];
            sRI[row*16 + slot] = bestI[mt*2 + h];
        }
    __syncthreads();
    if (t < BM) {
        float bv = sRV[t*16];
        int   bi = sRI[t*16];
        #pragma unroll
        for (int j = 1; j < 16; j++) {
            float v = sRV[t*16 + j];
            int   c = sRI[t*16 + j];
            if (v < bv || (v == bv && c < bi)) { bv = v; bi = c; }
        }
        sRI[t*16] = bi;
        atomicAdd(&g_counts[bi], 1);
    }
    __syncthreads();

    // gather + deterministic fp64 loss partial
    const int grow = t >> 1, part = t & 1;
    const int best = sRI[grow*16];
    const float4* qs = (const float4*)(cb + (size_t)best*DIMS) + part*32;
    const float4* xs = (const float4*)(x + (size_t)(rowBase + grow)*DIMS) + part*32;
    float4* qd = (float4*)(out + (size_t)(rowBase + grow)*DIMS) + part*32;
    double lsum = 0.0;
    #pragma unroll
    for (int u = 0; u < 32; u++) {
        float4 q = qs[u], xv = xs[u];
        float d0 = q.x - xv.x, d1 = q.y - xv.y, d2 = q.z - xv.z, d3 = q.w - xv.w;
        lsum += (double)d0*d0 + (double)d1*d1 + (double)d2*d2 + (double)d3*d3;
        qd[u] = q;
    }
    #pragma unroll
    for (int o = 16; o > 0; o >>= 1) lsum += __shfl_down_sync(0xffffffffu, lsum, o);
    double* sRed = (double*)(sm + OFF_LOSS);
    if (lane == 0) sRed[w] = lsum;
    __syncthreads();
    if (t == 0) {
        double sa = 0.0;
        #pragma unroll
        for (int k = 0; k < 8; k++) sa += sRed[k];
        g_lossPartial[blockIdx.x] = sa;
    }
}

__global__ void k_final(float* __restrict__ out, int out_size) {
    __shared__ double red[256];
    int t = threadIdx.x;
    double ls = 0.0;
    for (int i = t; i < NCTAS; i += 256) ls += g_lossPartial[i];
    red[t] = ls;
    __syncthreads();
    for (int o = 128; o > 0; o >>= 1) { if (t < o) red[t] += red[t + o]; __syncthreads(); }
    double lossTot = red[0];
    __syncthreads();
    double es = 0.0;
    for (int i = t; i < CODES; i += 256) {
        double p = (double)g_counts[i] * (1.0 / (double)NROWS);
        es += p * log(p + 1e-10);
    }
    red[t] = es;
    __syncthreads();
    for (int o = 128; o > 0; o >>= 1) { if (t < o) red[t] += red[t + o]; __syncthreads(); }
    if (t == 0 && out_size >= NROWS * DIMS + 2) {
        double mse = lossTot / (double)((size_t)NROWS * DIMS);
        out[NROWS * DIMS]     = (float)(mse * 1.25);
        out[NROWS * DIMS + 1] = (float)exp(-red[0]);
    }
}

extern "C" void kernel_launch(void* const* d_in, const int* in_sizes, int n_in,
                              void* d_out, int out_size) {
    const float* x  = (const float*)d_in[0];
    const float* cb = (const float*)d_in[1];
    if (n_in >= 2 && in_sizes[0] == CODES * DIMS && in_sizes[1] == NROWS * DIMS) {
        const float* tmp = x; x = cb; cb = tmp;
    }
    float* out = (float*)d_out;

    cudaFuncSetAttribute(k_tc, cudaFuncAttributeMaxDynamicSharedMemorySize, SMEM_SZ);

    k_setup<<<(NROWS + 255) / 256, 256>>>(x, cb);
    k_prep<<<((NROWS + CODES) * DIMS / 4 + 255) / 256, 256>>>(x, cb);
    k_tc<<<NCTAS, 256, SMEM_SZ>>>(x, cb, out);
    k_final<<<1, 256>>>(out, out_size);
}